// round 7
// baseline (speedup 1.0000x reference)
#include <cuda_runtime.h>
#include <math.h>

#define Bn   8
#define Cc   256
#define Ls   2048
#define NH   4
#define DH   32
#define HID  128
#define NQKV 384   // stacked Q(128) K(128) V(128) rows
#define JSTR 36    // smem row stride for transposed K/V tiles (16B aligned, conflict-free)

// Scratch (allocation-free rule: __device__ globals)
__device__ float g_qkv[(size_t)Bn * NQKV * Ls];   // [B][384][L], 25.2 MB
__device__ float g_att[(size_t)Bn * HID * Ls];    // [B][128][L], 8.4 MB

// ---------------- packed f32x2 helpers (Blackwell FFMA2 path) ----------------
__device__ __forceinline__ unsigned long long fma2(unsigned long long a,
                                                   unsigned long long b,
                                                   unsigned long long c) {
    unsigned long long d;
    asm("fma.rn.f32x2 %0, %1, %2, %3;" : "=l"(d) : "l"(a), "l"(b), "l"(c));
    return d;
}
__device__ __forceinline__ unsigned long long mul2(unsigned long long a,
                                                   unsigned long long b) {
    unsigned long long d;
    asm("mul.rn.f32x2 %0, %1, %2;" : "=l"(d) : "l"(a), "l"(b));
    return d;
}
__device__ __forceinline__ unsigned long long pack2(float x, float y) {
    unsigned long long d;
    asm("mov.b64 %0, {%1, %2};" : "=l"(d) : "r"(__float_as_uint(x)), "r"(__float_as_uint(y)));
    return d;
}
__device__ __forceinline__ float2 unpack2(unsigned long long v) {
    unsigned int x, y;
    asm("mov.b64 {%0, %1}, %2;" : "=r"(x), "=r"(y) : "l"(v));
    return make_float2(__uint_as_float(x), __uint_as_float(y));
}

// ---------------------------------------------------------------------------
// Kernel 1: channel LayerNorm (dim C) fused with QKV projection.
// Block: 256 threads, one batch x 64 L-columns. Weight chunks of 32 rows so
// smem ~102 KB -> 2 CTAs/SM.
// ---------------------------------------------------------------------------
__global__ __launch_bounds__(256, 2) void k_ln_qkv(
    const float* __restrict__ x, const float* __restrict__ gw,
    const float* __restrict__ bw,
    const float* __restrict__ Wq, const float* __restrict__ Wk,
    const float* __restrict__ Wv)
{
    extern __shared__ float sm[];
    float* xs    = sm;                 // [256][65]
    float* ws    = xs + 256 * 65;      // [32][257]
    float* red   = ws + 32 * 257;      // 512
    float* stats = red + 512;          // mean[64], rstd[64]

    const int tid = threadIdx.x;
    const int b   = blockIdx.y;
    const int l0  = blockIdx.x * 64;
    const float* xb = x + ((size_t)b * Cc) * Ls + l0;

    // load x tile [256 c][64 l]
    #pragma unroll
    for (int k = 0; k < 64; k++) {
        int idx = tid + k * 256;
        int c = idx >> 6, ll = idx & 63;
        xs[c * 65 + ll] = xb[(size_t)c * Ls + ll];
    }
    __syncthreads();

    // per-column mean/var (biased) over C=256
    {
        int ll = tid & 63, part = tid >> 6;
        float s = 0.f, s2 = 0.f;
        for (int c = part; c < 256; c += 4) {
            float v = xs[c * 65 + ll];
            s += v; s2 += v * v;
        }
        red[part * 64 + ll]       = s;
        red[256 + part * 64 + ll] = s2;
    }
    __syncthreads();
    if (tid < 64) {
        float ts  = red[tid] + red[64 + tid] + red[128 + tid] + red[192 + tid];
        float ts2 = red[256 + tid] + red[320 + tid] + red[384 + tid] + red[448 + tid];
        float mean = ts * (1.f / 256.f);
        float var  = ts2 * (1.f / 256.f) - mean * mean;
        stats[tid]      = mean;
        stats[64 + tid] = rsqrtf(var + 1e-5f);
    }
    __syncthreads();

    // normalize in place (+ affine g,b)
    #pragma unroll
    for (int k = 0; k < 64; k++) {
        int idx = tid + k * 256;
        int c = idx >> 6, ll = idx & 63;
        float m = stats[ll], r = stats[64 + ll];
        xs[c * 65 + ll] = (xs[c * 65 + ll] - m) * r * gw[c] + bw[c];
    }
    __syncthreads();

    // GEMM: out[n][l] = sum_c W[n][c] * xs[c][l], n in 12 chunks of 32
    const int tx = tid & 15, ty = tid >> 4;   // l-group, n-group (2 rows each)
    for (int nc = 0; nc < 12; nc++) {
        #pragma unroll
        for (int k = 0; k < 32; k++) {
            int idx = tid + k * 256;
            int nn = idx >> 8, c = idx & 255;
            int n = nc * 32 + nn;
            const float* wrow;
            if (n < 128)      wrow = Wq + (size_t)n * 256;
            else if (n < 256) wrow = Wk + (size_t)(n - 128) * 256;
            else              wrow = Wv + (size_t)(n - 256) * 256;
            ws[nn * 257 + c] = wrow[c];
        }
        __syncthreads();

        float acc[2][4] = {};
        #pragma unroll 8
        for (int c = 0; c < 256; c++) {
            float a0 = xs[c * 65 + tx * 4 + 0];
            float a1 = xs[c * 65 + tx * 4 + 1];
            float a2 = xs[c * 65 + tx * 4 + 2];
            float a3 = xs[c * 65 + tx * 4 + 3];
            float w0 = ws[(ty * 2 + 0) * 257 + c];
            float w1 = ws[(ty * 2 + 1) * 257 + c];
            acc[0][0] += w0 * a0; acc[0][1] += w0 * a1;
            acc[0][2] += w0 * a2; acc[0][3] += w0 * a3;
            acc[1][0] += w1 * a0; acc[1][1] += w1 * a1;
            acc[1][2] += w1 * a2; acc[1][3] += w1 * a3;
        }
        float* outb = g_qkv + ((size_t)b * NQKV + nc * 32) * Ls + l0;
        #pragma unroll
        for (int j = 0; j < 2; j++) {
            float4 v = make_float4(acc[j][0], acc[j][1], acc[j][2], acc[j][3]);
            *(float4*)(outb + (size_t)(ty * 2 + j) * Ls + tx * 4) = v;
        }
        __syncthreads();
    }
}

// ---------------------------------------------------------------------------
// Kernel 2: flash attention per (b, h, 64-query tile). Block = 256 threads.
// Quad of 4 lanes owns one query i; j interleaved across quad (j = q + 4*jj).
// K/V tiles stored TRANSPOSED [j][d] (stride JSTR) -> LDS.128 yields packed
// f32x2 operands for FFMA2. Global K/V loads are register double-buffered so
// LDG latency overlaps the previous tile's compute.
// ---------------------------------------------------------------------------
__global__ __launch_bounds__(256, 2) void k_attn()
{
    __shared__ float Ks[64 * JSTR];
    __shared__ float Vs[64 * JSTR];

    const int tid = threadIdx.x;
    const int b = blockIdx.z, h = blockIdx.y;
    const int i0 = blockIdx.x * 64;
    const int q  = tid & 3;        // quad lane
    const int il = tid >> 2;       // query within tile (0..63)

    const float* Qg = g_qkv + ((size_t)b * NQKV + h * DH) * Ls;
    const float* Kg = g_qkv + ((size_t)b * NQKV + HID + h * DH) * Ls;
    const float* Vg = g_qkv + ((size_t)b * NQKV + 2 * HID + h * DH) * Ls;

    const float scale = 0.1767766952966369f;  // 32^-0.5
    unsigned long long Qr2[16];
    #pragma unroll
    for (int k = 0; k < 16; k++) {
        float q0 = Qg[(size_t)(2 * k)     * Ls + i0 + il] * scale;
        float q1 = Qg[(size_t)(2 * k + 1) * Ls + i0 + il] * scale;
        Qr2[k] = pack2(q0, q1);
    }

    unsigned long long acc2[16];
    #pragma unroll
    for (int k = 0; k < 16; k++) acc2[k] = 0ull;
    float mrun = -1e30f, lrun = 0.f;

    // staging indices: each thread loads float4 along j for 2 d's (K and V)
    const int sd  = tid >> 4;         // d 0..15 (and +16)
    const int sj4 = (tid & 15) * 4;   // j base

    // prefetch tile 0
    float4 pk0 = *(const float4*)(Kg + (size_t)sd * Ls + sj4);
    float4 pk1 = *(const float4*)(Kg + (size_t)(sd + 16) * Ls + sj4);
    float4 pv0 = *(const float4*)(Vg + (size_t)sd * Ls + sj4);
    float4 pv1 = *(const float4*)(Vg + (size_t)(sd + 16) * Ls + sj4);

    for (int j0 = 0; j0 < Ls; j0 += 64) {
        __syncthreads();   // consumers of previous tile done
        {
            Ks[(sj4 + 0) * JSTR + sd] = pk0.x;  Ks[(sj4 + 1) * JSTR + sd] = pk0.y;
            Ks[(sj4 + 2) * JSTR + sd] = pk0.z;  Ks[(sj4 + 3) * JSTR + sd] = pk0.w;
            Ks[(sj4 + 0) * JSTR + sd + 16] = pk1.x;  Ks[(sj4 + 1) * JSTR + sd + 16] = pk1.y;
            Ks[(sj4 + 2) * JSTR + sd + 16] = pk1.z;  Ks[(sj4 + 3) * JSTR + sd + 16] = pk1.w;
            Vs[(sj4 + 0) * JSTR + sd] = pv0.x;  Vs[(sj4 + 1) * JSTR + sd] = pv0.y;
            Vs[(sj4 + 2) * JSTR + sd] = pv0.z;  Vs[(sj4 + 3) * JSTR + sd] = pv0.w;
            Vs[(sj4 + 0) * JSTR + sd + 16] = pv1.x;  Vs[(sj4 + 1) * JSTR + sd + 16] = pv1.y;
            Vs[(sj4 + 2) * JSTR + sd + 16] = pv1.z;  Vs[(sj4 + 3) * JSTR + sd + 16] = pv1.w;
        }
        __syncthreads();

        // issue next tile's global loads NOW; latency hides under compute
        if (j0 + 64 < Ls) {
            const int jn = j0 + 64;
            pk0 = *(const float4*)(Kg + (size_t)sd * Ls + jn + sj4);
            pk1 = *(const float4*)(Kg + (size_t)(sd + 16) * Ls + jn + sj4);
            pv0 = *(const float4*)(Vg + (size_t)sd * Ls + jn + sj4);
            pv1 = *(const float4*)(Vg + (size_t)(sd + 16) * Ls + jn + sj4);
        }

        // scores: s[jj] = sum_d Qr[d] * K[j][d], j = q + 4*jj
        float s[16];
        #pragma unroll
        for (int jj = 0; jj < 16; jj++) {
            const int j = q + jj * 4;
            const ulonglong2* kr = (const ulonglong2*)(Ks + j * JSTR);
            unsigned long long sa = 0ull, sb = 0ull;
            #pragma unroll
            for (int k = 0; k < 8; k++) {
                ulonglong2 kk = kr[k];
                sa = fma2(Qr2[2 * k],     kk.x, sa);
                sb = fma2(Qr2[2 * k + 1], kk.y, sb);
            }
            float2 fa = unpack2(sa), fb = unpack2(sb);
            s[jj] = (fa.x + fa.y) + (fb.x + fb.y);
        }
        float tmax = s[0];
        #pragma unroll
        for (int jj = 1; jj < 16; jj++) tmax = fmaxf(tmax, s[jj]);
        tmax = fmaxf(tmax, __shfl_xor_sync(0xffffffffu, tmax, 1));
        tmax = fmaxf(tmax, __shfl_xor_sync(0xffffffffu, tmax, 2));

        float nm   = fmaxf(mrun, tmax);
        float corr = __expf(mrun - nm);
        float ps   = 0.f;
        #pragma unroll
        for (int jj = 0; jj < 16; jj++) { s[jj] = __expf(s[jj] - nm); ps += s[jj]; }
        ps += __shfl_xor_sync(0xffffffffu, ps, 1);
        ps += __shfl_xor_sync(0xffffffffu, ps, 2);
        lrun = lrun * corr + ps;
        mrun = nm;

        const unsigned long long c2 = pack2(corr, corr);
        #pragma unroll
        for (int k = 0; k < 16; k++) acc2[k] = mul2(acc2[k], c2);

        #pragma unroll
        for (int jj = 0; jj < 16; jj++) {
            const int j = q + jj * 4;
            const unsigned long long pp = pack2(s[jj], s[jj]);
            const ulonglong2* vr = (const ulonglong2*)(Vs + j * JSTR);
            #pragma unroll
            for (int k = 0; k < 8; k++) {
                ulonglong2 vv = vr[k];
                acc2[2 * k]     = fma2(pp, vv.x, acc2[2 * k]);
                acc2[2 * k + 1] = fma2(pp, vv.y, acc2[2 * k + 1]);
            }
        }
    }

    // unpack, reduce partial O over the quad
    float acc[32];
    #pragma unroll
    for (int k = 0; k < 16; k++) {
        float2 f = unpack2(acc2[k]);
        acc[2 * k] = f.x; acc[2 * k + 1] = f.y;
    }
    #pragma unroll
    for (int d = 0; d < 32; d++) {
        acc[d] += __shfl_xor_sync(0xffffffffu, acc[d], 1);
        acc[d] += __shfl_xor_sync(0xffffffffu, acc[d], 2);
    }
    if (q == 0) {
        float inv = 1.f / lrun;
        float* Og = g_att + ((size_t)b * HID + h * DH) * Ls + i0 + il;
        #pragma unroll
        for (int d = 0; d < 32; d++)
            Og[(size_t)d * Ls] = acc[d] * inv;
    }
}

// ---------------------------------------------------------------------------
// Kernel 3: y = Wo @ att + bo + x (residual).  Weight chunks of 32 rows.
// ---------------------------------------------------------------------------
__global__ __launch_bounds__(256, 3) void k_out(
    const float* __restrict__ Wo, const float* __restrict__ bo,
    const float* __restrict__ x, float* __restrict__ y)
{
    extern __shared__ float sm[];
    float* Ot = sm;              // [128][65]
    float* ws = Ot + 128 * 65;   // [32][129]

    const int tid = threadIdx.x;
    const int b = blockIdx.y;
    const int l0 = blockIdx.x * 64;
    const float* Ob = g_att + ((size_t)b * HID) * Ls + l0;

    #pragma unroll
    for (int k = 0; k < 32; k++) {
        int idx = tid + k * 256;
        int n = idx >> 6, ll = idx & 63;
        Ot[n * 65 + ll] = Ob[(size_t)n * Ls + ll];
    }
    __syncthreads();

    const int tx = tid & 15, ty = tid >> 4;
    for (int oc = 0; oc < 8; oc++) {
        #pragma unroll
        for (int k = 0; k < 16; k++) {
            int idx = tid + k * 256;
            int nn = idx >> 7, c = idx & 127;
            ws[nn * 129 + c] = Wo[(size_t)(oc * 32 + nn) * 128 + c];
        }
        __syncthreads();

        float acc[2][4] = {};
        #pragma unroll 8
        for (int c = 0; c < 128; c++) {
            float a0 = Ot[c * 65 + tx * 4 + 0];
            float a1 = Ot[c * 65 + tx * 4 + 1];
            float a2 = Ot[c * 65 + tx * 4 + 2];
            float a3 = Ot[c * 65 + tx * 4 + 3];
            float w0 = ws[(ty * 2 + 0) * 129 + c];
            float w1 = ws[(ty * 2 + 1) * 129 + c];
            acc[0][0] += w0 * a0; acc[0][1] += w0 * a1;
            acc[0][2] += w0 * a2; acc[0][3] += w0 * a3;
            acc[1][0] += w1 * a0; acc[1][1] += w1 * a1;
            acc[1][2] += w1 * a2; acc[1][3] += w1 * a3;
        }

        const float* xb = x + ((size_t)b * Cc + oc * 32) * Ls + l0;
        float*       yb = y + ((size_t)b * Cc + oc * 32) * Ls + l0;
        #pragma unroll
        for (int j = 0; j < 2; j++) {
            int o = oc * 32 + ty * 2 + j;
            float bias = bo[o];
            size_t off = (size_t)(ty * 2 + j) * Ls + tx * 4;
            float4 xr = *(const float4*)(xb + off);
            float4 v  = make_float4(acc[j][0] + bias + xr.x,
                                    acc[j][1] + bias + xr.y,
                                    acc[j][2] + bias + xr.z,
                                    acc[j][3] + bias + xr.w);
            *(float4*)(yb + off) = v;
        }
        __syncthreads();
    }
}

// ---------------------------------------------------------------------------
extern "C" void kernel_launch(void* const* d_in, const int* in_sizes, int n_in,
                              void* d_out, int out_size)
{
    const float* x  = (const float*)d_in[0];
    const float* gw = (const float*)d_in[1];
    const float* bw = (const float*)d_in[2];
    const float* Wq = (const float*)d_in[3];
    const float* Wk = (const float*)d_in[4];
    const float* Wv = (const float*)d_in[5];
    const float* Wo = (const float*)d_in[6];
    const float* bo = (const float*)d_in[7];
    float* y = (float*)d_out;

    const int smem1 = (256 * 65 + 32 * 257 + 512 + 128) * sizeof(float); // ~102 KB
    const int smem3 = (128 * 65 + 32 * 129) * sizeof(float);             // ~50 KB
    cudaFuncSetAttribute(k_ln_qkv, cudaFuncAttributeMaxDynamicSharedMemorySize, smem1);
    cudaFuncSetAttribute(k_out,    cudaFuncAttributeMaxDynamicSharedMemorySize, smem3);

    k_ln_qkv<<<dim3(32, 8), 256, smem1>>>(x, gw, bw, Wq, Wk, Wv);
    k_attn  <<<dim3(32, 4, 8), 256>>>();
    k_out   <<<dim3(32, 8), 256, smem3>>>(Wo, bo, x, y);
}

// round 17
// speedup vs baseline: 2.7535x; 2.7535x over previous
#include <cuda_runtime.h>
#include <cuda_bf16.h>
#include <stdint.h>
#include <math.h>

#define Bn   8
#define Cc   256
#define Ls   2048
#define NH   4
#define DH   32
#define HID  128
#define KTS  40    // K-tile smem row stride (halves): bank-conflict-free for B-frag reads
#define VTS  72    // V-tile smem row stride (halves)

// Scratch (__device__ globals per allocation rules)
__device__ float         g_q   [(size_t)Bn * HID * Ls];   // Q fp32 [b][n=h*32+d][l]
__device__ __nv_bfloat16 g_kt_hi[(size_t)Bn * Ls * HID];  // K^T bf16 hi [b][l][n]
__device__ __nv_bfloat16 g_kt_lo[(size_t)Bn * Ls * HID];  // K^T bf16 lo
__device__ __nv_bfloat16 g_v_hi [(size_t)Bn * HID * Ls];  // V bf16 hi [b][n][l]
__device__ __nv_bfloat16 g_v_lo [(size_t)Bn * HID * Ls];  // V bf16 lo
__device__ float         g_att [(size_t)Bn * HID * Ls];   // attention out fp32 [b][n][l]

// ---------------- bf16 split helpers ----------------
__device__ __forceinline__ uint32_t packbf2(float lo, float hi) {
    uint32_t d;
    asm("cvt.rn.bf16x2.f32 %0, %1, %2;" : "=r"(d) : "f"(hi), "f"(lo));
    return d;
}
// split (x0,x1) into packed bf16x2 hi + lo planes (x = hi + lo)
__device__ __forceinline__ void split2(float x0, float x1, uint32_t& hp, uint32_t& lp) {
    hp = packbf2(x0, x1);
    float h0 = __uint_as_float(hp << 16);
    float h1 = __uint_as_float(hp & 0xffff0000u);
    lp = packbf2(x0 - h0, x1 - h1);
}
// D += A(16x16 bf16) * B(16x8 bf16), fp32 accum
__device__ __forceinline__ void mma16816(float* c, const uint32_t* a, uint32_t b0, uint32_t b1) {
    asm("mma.sync.aligned.m16n8k16.row.col.f32.bf16.bf16.f32 "
        "{%0,%1,%2,%3}, {%4,%5,%6,%7}, {%8,%9}, {%0,%1,%2,%3};"
        : "+f"(c[0]), "+f"(c[1]), "+f"(c[2]), "+f"(c[3])
        : "r"(a[0]), "r"(a[1]), "r"(a[2]), "r"(a[3]), "r"(b0), "r"(b1));
}

// ---------------------------------------------------------------------------
// Kernel 1: channel LayerNorm + QKV projection.
// Q -> fp32 [n][l];  K -> bf16 hi/lo TRANSPOSED [l][n];  V -> bf16 hi/lo [n][l].
// ---------------------------------------------------------------------------
__global__ __launch_bounds__(256, 2) void k_ln_qkv(
    const float* __restrict__ x, const float* __restrict__ gw,
    const float* __restrict__ bw,
    const float* __restrict__ Wq, const float* __restrict__ Wk,
    const float* __restrict__ Wv)
{
    extern __shared__ float sm[];
    float* xs    = sm;                 // [256][65]
    float* ws    = xs + 256 * 65;      // [32][257]
    float* red   = ws + 32 * 257;      // 512
    float* stats = red + 512;          // mean[64], rstd[64]

    const int tid = threadIdx.x;
    const int b   = blockIdx.y;
    const int l0  = blockIdx.x * 64;
    const float* xb = x + ((size_t)b * Cc) * Ls + l0;

    #pragma unroll
    for (int k = 0; k < 64; k++) {
        int idx = tid + k * 256;
        int c = idx >> 6, ll = idx & 63;
        xs[c * 65 + ll] = xb[(size_t)c * Ls + ll];
    }
    __syncthreads();

    {
        int ll = tid & 63, part = tid >> 6;
        float s = 0.f, s2 = 0.f;
        for (int c = part; c < 256; c += 4) {
            float v = xs[c * 65 + ll];
            s += v; s2 += v * v;
        }
        red[part * 64 + ll]       = s;
        red[256 + part * 64 + ll] = s2;
    }
    __syncthreads();
    if (tid < 64) {
        float ts  = red[tid] + red[64 + tid] + red[128 + tid] + red[192 + tid];
        float ts2 = red[256 + tid] + red[320 + tid] + red[384 + tid] + red[448 + tid];
        float mean = ts * (1.f / 256.f);
        float var  = ts2 * (1.f / 256.f) - mean * mean;
        stats[tid]      = mean;
        stats[64 + tid] = rsqrtf(var + 1e-5f);
    }
    __syncthreads();

    #pragma unroll
    for (int k = 0; k < 64; k++) {
        int idx = tid + k * 256;
        int c = idx >> 6, ll = idx & 63;
        float m = stats[ll], r = stats[64 + ll];
        xs[c * 65 + ll] = (xs[c * 65 + ll] - m) * r * gw[c] + bw[c];
    }
    __syncthreads();

    const int tx = tid & 15, ty = tid >> 4;   // l-group, n-group
    for (int nc = 0; nc < 12; nc++) {
        #pragma unroll
        for (int k = 0; k < 32; k++) {
            int idx = tid + k * 256;
            int nn = idx >> 8, c = idx & 255;
            int n = nc * 32 + nn;
            const float* wrow;
            if (n < 128)      wrow = Wq + (size_t)n * 256;
            else if (n < 256) wrow = Wk + (size_t)(n - 128) * 256;
            else              wrow = Wv + (size_t)(n - 256) * 256;
            ws[nn * 257 + c] = wrow[c];
        }
        __syncthreads();

        float acc[2][4] = {};
        #pragma unroll 8
        for (int c = 0; c < 256; c++) {
            float a0 = xs[c * 65 + tx * 4 + 0];
            float a1 = xs[c * 65 + tx * 4 + 1];
            float a2 = xs[c * 65 + tx * 4 + 2];
            float a3 = xs[c * 65 + tx * 4 + 3];
            float w0 = ws[(ty * 2 + 0) * 257 + c];
            float w1 = ws[(ty * 2 + 1) * 257 + c];
            acc[0][0] += w0 * a0; acc[0][1] += w0 * a1;
            acc[0][2] += w0 * a2; acc[0][3] += w0 * a3;
            acc[1][0] += w1 * a0; acc[1][1] += w1 * a1;
            acc[1][2] += w1 * a2; acc[1][3] += w1 * a3;
        }

        if (nc < 4) {
            // Q: fp32, [n][l]
            float* outb = g_q + ((size_t)b * HID + nc * 32) * Ls + l0;
            #pragma unroll
            for (int j = 0; j < 2; j++) {
                float4 v = make_float4(acc[j][0], acc[j][1], acc[j][2], acc[j][3]);
                *(float4*)(outb + (size_t)(ty * 2 + j) * Ls + tx * 4) = v;
            }
        } else if (nc < 8) {
            // K: bf16 hi/lo, transposed [l][n]
            int kbase = (nc - 4) * 32;
            #pragma unroll
            for (int j = 0; j < 2; j++) {
                int n = kbase + ty * 2 + j;
                #pragma unroll
                for (int i = 0; i < 4; i++) {
                    float v = acc[j][i];
                    __nv_bfloat16 hi = __float2bfloat16(v);
                    __nv_bfloat16 lo = __float2bfloat16(v - __bfloat162float(hi));
                    size_t idx = (size_t)b * Ls * HID + (size_t)(l0 + tx * 4 + i) * HID + n;
                    g_kt_hi[idx] = hi;
                    g_kt_lo[idx] = lo;
                }
            }
        } else {
            // V: bf16 hi/lo, [n][l]
            int vbase = (nc - 8) * 32;
            #pragma unroll
            for (int j = 0; j < 2; j++) {
                int n = vbase + ty * 2 + j;
                size_t base = (size_t)b * HID * Ls + (size_t)n * Ls + l0 + tx * 4;
                __nv_bfloat16 h0 = __float2bfloat16(acc[j][0]);
                __nv_bfloat16 h1 = __float2bfloat16(acc[j][1]);
                __nv_bfloat16 h2 = __float2bfloat16(acc[j][2]);
                __nv_bfloat16 h3 = __float2bfloat16(acc[j][3]);
                __nv_bfloat16 e0 = __float2bfloat16(acc[j][0] - __bfloat162float(h0));
                __nv_bfloat16 e1 = __float2bfloat16(acc[j][1] - __bfloat162float(h1));
                __nv_bfloat16 e2 = __float2bfloat16(acc[j][2] - __bfloat162float(h2));
                __nv_bfloat16 e3 = __float2bfloat16(acc[j][3] - __bfloat162float(h3));
                ((__nv_bfloat162*)(g_v_hi + base))[0] = __nv_bfloat162(h0, h1);
                ((__nv_bfloat162*)(g_v_hi + base))[1] = __nv_bfloat162(h2, h3);
                ((__nv_bfloat162*)(g_v_lo + base))[0] = __nv_bfloat162(e0, e1);
                ((__nv_bfloat162*)(g_v_lo + base))[1] = __nv_bfloat162(e2, e3);
            }
        }
        __syncthreads();
    }
}

// ---------------------------------------------------------------------------
// Kernel 2: flash attention, bf16 mma.sync with 3-term split compensation.
// CTA = 128 threads (4 warps); warp owns 16 query rows; CTA i-tile = 64.
// j loop over 64-wide K/V tiles staged in smem (hi+lo planes).
// ---------------------------------------------------------------------------
__global__ __launch_bounds__(128, 4) void k_attn()
{
    __shared__ __align__(16) __nv_bfloat16 Kh[64 * KTS];
    __shared__ __align__(16) __nv_bfloat16 Kl[64 * KTS];
    __shared__ __align__(16) __nv_bfloat16 Vh[32 * VTS];
    __shared__ __align__(16) __nv_bfloat16 Vl[32 * VTS];

    const int tid  = threadIdx.x;
    const int warp = tid >> 5, lane = tid & 31;
    const int g  = lane >> 2;      // fragment row group
    const int tg = lane & 3;       // fragment col group
    const int b = blockIdx.z, h = blockIdx.y;
    const int i0 = blockIdx.x * 64 + warp * 16;

    const float scale = 0.1767766952966369f;  // 32^-0.5
    const float* Qg = g_q + ((size_t)b * HID + h * DH) * Ls;
    const __nv_bfloat16* kh_g = g_kt_hi + (size_t)b * Ls * HID + h * DH;
    const __nv_bfloat16* kl_g = g_kt_lo + (size_t)b * Ls * HID + h * DH;
    const __nv_bfloat16* vh_g = g_v_hi + ((size_t)b * HID + h * DH) * Ls;
    const __nv_bfloat16* vl_g = g_v_lo + ((size_t)b * HID + h * DH) * Ls;

    // Q A-fragments (2 k16 chunks covering d=0..31), fp32 loads -> scale -> split
    uint32_t qa_hi[2][4], qa_lo[2][4];
    #pragma unroll
    for (int kt = 0; kt < 2; kt++) {
        #pragma unroll
        for (int rr = 0; rr < 4; rr++) {
            int row = i0 + g + ((rr & 1) ? 8 : 0);
            int col = kt * 16 + tg * 2 + ((rr & 2) ? 8 : 0);
            float f0 = Qg[(size_t)col * Ls + row] * scale;
            float f1 = Qg[(size_t)(col + 1) * Ls + row] * scale;
            split2(f0, f1, qa_hi[kt][rr], qa_lo[kt][rr]);
        }
    }

    float m_[2] = { -1e30f, -1e30f };
    float l_[2] = { 0.f, 0.f };
    float of[4][4];
    #pragma unroll
    for (int dt = 0; dt < 4; dt++)
        #pragma unroll
        for (int r = 0; r < 4; r++) of[dt][r] = 0.f;

    for (int j0 = 0; j0 < Ls; j0 += 64) {
        __syncthreads();
        // stage K^T tile [64 j][32 d] hi+lo (uint4 = 8 halves)
        #pragma unroll
        for (int idx = tid; idx < 256; idx += 128) {
            int r = idx >> 2, p = idx & 3;
            const size_t go = (size_t)(j0 + r) * HID + p * 8;
            *(uint4*)&Kh[r * KTS + p * 8] = *(const uint4*)(kh_g + go);
            *(uint4*)&Kl[r * KTS + p * 8] = *(const uint4*)(kl_g + go);
        }
        // stage V tile [32 d][64 j] hi+lo
        #pragma unroll
        for (int idx = tid; idx < 256; idx += 128) {
            int r = idx >> 3, p = idx & 7;
            const size_t go = (size_t)r * Ls + j0 + p * 8;
            *(uint4*)&Vh[r * VTS + p * 8] = *(const uint4*)(vh_g + go);
            *(uint4*)&Vl[r * VTS + p * 8] = *(const uint4*)(vl_g + go);
        }
        __syncthreads();

        // S = Q K^T  (8 n8 j-tiles, k = 32 via 2 k16, 3 split terms)
        float sc[8][4];
        #pragma unroll
        for (int t8 = 0; t8 < 8; t8++) {
            sc[t8][0] = sc[t8][1] = sc[t8][2] = sc[t8][3] = 0.f;
            #pragma unroll
            for (int kt = 0; kt < 2; kt++) {
                int roff = (t8 * 8 + g) * KTS + kt * 16 + tg * 2;
                uint32_t bh0 = *(const uint32_t*)&Kh[roff];
                uint32_t bh1 = *(const uint32_t*)&Kh[roff + 8];
                uint32_t bl0 = *(const uint32_t*)&Kl[roff];
                uint32_t bl1 = *(const uint32_t*)&Kl[roff + 8];
                mma16816(sc[t8], qa_hi[kt], bh0, bh1);
                mma16816(sc[t8], qa_hi[kt], bl0, bl1);
                mma16816(sc[t8], qa_lo[kt], bh0, bh1);
            }
        }

        // online softmax (rows g and g+8; cols split over tg quad)
        float mx0 = sc[0][0], mx1 = sc[0][2];
        #pragma unroll
        for (int t8 = 0; t8 < 8; t8++) {
            mx0 = fmaxf(mx0, fmaxf(sc[t8][0], sc[t8][1]));
            mx1 = fmaxf(mx1, fmaxf(sc[t8][2], sc[t8][3]));
        }
        mx0 = fmaxf(mx0, __shfl_xor_sync(0xffffffffu, mx0, 1));
        mx0 = fmaxf(mx0, __shfl_xor_sync(0xffffffffu, mx0, 2));
        mx1 = fmaxf(mx1, __shfl_xor_sync(0xffffffffu, mx1, 1));
        mx1 = fmaxf(mx1, __shfl_xor_sync(0xffffffffu, mx1, 2));

        float nm0 = fmaxf(m_[0], mx0), nm1 = fmaxf(m_[1], mx1);
        float corr0 = __expf(m_[0] - nm0), corr1 = __expf(m_[1] - nm1);

        float ps0 = 0.f, ps1 = 0.f;
        #pragma unroll
        for (int t8 = 0; t8 < 8; t8++) {
            sc[t8][0] = __expf(sc[t8][0] - nm0);
            sc[t8][1] = __expf(sc[t8][1] - nm0);
            sc[t8][2] = __expf(sc[t8][2] - nm1);
            sc[t8][3] = __expf(sc[t8][3] - nm1);
            ps0 += sc[t8][0] + sc[t8][1];
            ps1 += sc[t8][2] + sc[t8][3];
        }
        ps0 += __shfl_xor_sync(0xffffffffu, ps0, 1);
        ps0 += __shfl_xor_sync(0xffffffffu, ps0, 2);
        ps1 += __shfl_xor_sync(0xffffffffu, ps1, 1);
        ps1 += __shfl_xor_sync(0xffffffffu, ps1, 2);
        l_[0] = l_[0] * corr0 + ps0;
        l_[1] = l_[1] * corr1 + ps1;
        m_[0] = nm0; m_[1] = nm1;

        #pragma unroll
        for (int dt = 0; dt < 4; dt++) {
            of[dt][0] *= corr0; of[dt][1] *= corr0;
            of[dt][2] *= corr1; of[dt][3] *= corr1;
        }

        // O += P V^T : for each k16 j-group build P A-frag (split), mma over 4 d-tiles
        #pragma unroll
        for (int jk = 0; jk < 4; jk++) {
            uint32_t pa_hi[4], pa_lo[4];
            split2(sc[2 * jk][0],     sc[2 * jk][1],     pa_hi[0], pa_lo[0]);
            split2(sc[2 * jk][2],     sc[2 * jk][3],     pa_hi[1], pa_lo[1]);
            split2(sc[2 * jk + 1][0], sc[2 * jk + 1][1], pa_hi[2], pa_lo[2]);
            split2(sc[2 * jk + 1][2], sc[2 * jk + 1][3], pa_hi[3], pa_lo[3]);
            #pragma unroll
            for (int dt = 0; dt < 4; dt++) {
                int roff = (dt * 8 + g) * VTS + jk * 16 + tg * 2;
                uint32_t bh0 = *(const uint32_t*)&Vh[roff];
                uint32_t bh1 = *(const uint32_t*)&Vh[roff + 8];
                uint32_t bl0 = *(const uint32_t*)&Vl[roff];
                uint32_t bl1 = *(const uint32_t*)&Vl[roff + 8];
                mma16816(of[dt], pa_hi, bh0, bh1);
                mma16816(of[dt], pa_hi, bl0, bl1);
                mma16816(of[dt], pa_lo, bh0, bh1);
            }
        }
    }

    // normalize and write O (fp32) to g_att [n=h*32+d][l]
    float inv0 = 1.f / l_[0], inv1 = 1.f / l_[1];
    float* Og = g_att + ((size_t)b * HID + h * DH) * Ls;
    #pragma unroll
    for (int dt = 0; dt < 4; dt++) {
        #pragma unroll
        for (int c = 0; c < 2; c++) {
            int d = dt * 8 + tg * 2 + c;
            Og[(size_t)d * Ls + i0 + g]     = of[dt][c]     * inv0;
            Og[(size_t)d * Ls + i0 + g + 8] = of[dt][2 + c] * inv1;
        }
    }
}

// ---------------------------------------------------------------------------
// Kernel 3: y = Wo @ att + bo + x (residual).
// ---------------------------------------------------------------------------
__global__ __launch_bounds__(256, 3) void k_out(
    const float* __restrict__ Wo, const float* __restrict__ bo,
    const float* __restrict__ x, float* __restrict__ y)
{
    extern __shared__ float sm[];
    float* Ot = sm;              // [128][65]
    float* ws = Ot + 128 * 65;   // [32][129]

    const int tid = threadIdx.x;
    const int b = blockIdx.y;
    const int l0 = blockIdx.x * 64;
    const float* Ob = g_att + ((size_t)b * HID) * Ls + l0;

    #pragma unroll
    for (int k = 0; k < 32; k++) {
        int idx = tid + k * 256;
        int n = idx >> 6, ll = idx & 63;
        Ot[n * 65 + ll] = Ob[(size_t)n * Ls + ll];
    }
    __syncthreads();

    const int tx = tid & 15, ty = tid >> 4;
    for (int oc = 0; oc < 8; oc++) {
        #pragma unroll
        for (int k = 0; k < 16; k++) {
            int idx = tid + k * 256;
            int nn = idx >> 7, c = idx & 127;
            ws[nn * 129 + c] = Wo[(size_t)(oc * 32 + nn) * 128 + c];
        }
        __syncthreads();

        float acc[2][4] = {};
        #pragma unroll 8
        for (int c = 0; c < 128; c++) {
            float a0 = Ot[c * 65 + tx * 4 + 0];
            float a1 = Ot[c * 65 + tx * 4 + 1];
            float a2 = Ot[c * 65 + tx * 4 + 2];
            float a3 = Ot[c * 65 + tx * 4 + 3];
            float w0 = ws[(ty * 2 + 0) * 129 + c];
            float w1 = ws[(ty * 2 + 1) * 129 + c];
            acc[0][0] += w0 * a0; acc[0][1] += w0 * a1;
            acc[0][2] += w0 * a2; acc[0][3] += w0 * a3;
            acc[1][0] += w1 * a0; acc[1][1] += w1 * a1;
            acc[1][2] += w1 * a2; acc[1][3] += w1 * a3;
        }

        const float* xb = x + ((size_t)b * Cc + oc * 32) * Ls + l0;
        float*       yb = y + ((size_t)b * Cc + oc * 32) * Ls + l0;
        #pragma unroll
        for (int j = 0; j < 2; j++) {
            int o = oc * 32 + ty * 2 + j;
            float bias = bo[o];
            size_t off = (size_t)(ty * 2 + j) * Ls + tx * 4;
            float4 xr = *(const float4*)(xb + off);
            float4 v  = make_float4(acc[j][0] + bias + xr.x,
                                    acc[j][1] + bias + xr.y,
                                    acc[j][2] + bias + xr.z,
                                    acc[j][3] + bias + xr.w);
            *(float4*)(yb + off) = v;
        }
        __syncthreads();
    }
}

// ---------------------------------------------------------------------------
extern "C" void kernel_launch(void* const* d_in, const int* in_sizes, int n_in,
                              void* d_out, int out_size)
{
    const float* x  = (const float*)d_in[0];
    const float* gw = (const float*)d_in[1];
    const float* bw = (const float*)d_in[2];
    const float* Wq = (const float*)d_in[3];
    const float* Wk = (const float*)d_in[4];
    const float* Wv = (const float*)d_in[5];
    const float* Wo = (const float*)d_in[6];
    const float* bo = (const float*)d_in[7];
    float* y = (float*)d_out;

    const int smem1 = (256 * 65 + 32 * 257 + 512 + 128) * sizeof(float); // ~102 KB
    const int smem3 = (128 * 65 + 32 * 129) * sizeof(float);             // ~50 KB
    cudaFuncSetAttribute(k_ln_qkv, cudaFuncAttributeMaxDynamicSharedMemorySize, smem1);
    cudaFuncSetAttribute(k_out,    cudaFuncAttributeMaxDynamicSharedMemorySize, smem3);

    k_ln_qkv<<<dim3(32, 8), 256, smem1>>>(x, gw, bw, Wq, Wk, Wv);
    k_attn  <<<dim3(32, NH, Bn), 128>>>();
    k_out   <<<dim3(32, 8), 256, smem3>>>(Wo, bo, x, y);
}